// round 7
// baseline (speedup 1.0000x reference)
#include <cuda_runtime.h>
#include <float.h>
#include <stdint.h>

#define MAXN 12000
#define KNN  20

// ---------------- scratch (static device globals; no runtime allocation) ---
__device__ float g_D[(size_t)MAXN * MAXN];      // 576 MB distance matrix (reused)
__device__ int   g_idx[MAXN * KNN];
__device__ float g_X0[MAXN * 4];
__device__ float g_X14[MAXN * 256];             // x1|x2|x3|x4 concatenated
__device__ float g_Y5[(size_t)MAXN * 1024];
__device__ float g_F[MAXN * 256];

// ---------------- pairwise squared distances, direct (cancellation-free) ---
// D[m,n] = sum_c (A[m,c] - A[n,c])^2, tiled 64x64, FSUB+FFMA inner loop.
// Near-exact for ranking: error ~1e-7 RELATIVE to the (small) distance.
#define TBM 64
#define TBN 64
#define TBK 16

__global__ void __launch_bounds__(256) sqdist_nt(
    const float* __restrict__ A, int lda,
    float* __restrict__ D, int ldc,
    int N, int Kd)
{
    __shared__ __align__(16) float As[TBK][TBM];
    __shared__ __align__(16) float Bs[TBK][TBN];

    int tid = threadIdx.x;
    int bm = blockIdx.y * TBM;
    int bn = blockIdx.x * TBN;
    int tx = tid & 15;
    int ty = tid >> 4;
    int lr = tid >> 2;
    int lk = (tid & 3) * 4;

    float acc[4][4];
#pragma unroll
    for (int i = 0; i < 4; i++)
#pragma unroll
        for (int j = 0; j < 4; j++) acc[i][j] = 0.f;

    int am  = bm + lr;
    int bnr = bn + lr;

    for (int k0 = 0; k0 < Kd; k0 += TBK) {
#pragma unroll
        for (int i = 0; i < 4; i++) {
            int k = k0 + lk + i;
            // out-of-range rows load 0 in BOTH tiles -> diff may be garbage only
            // for rows we never store; in-range pairs always use real data.
            As[lk + i][lr] = (am  < N && k < Kd) ? A[(size_t)am  * lda + k] : 0.f;
            Bs[lk + i][lr] = (bnr < N && k < Kd) ? A[(size_t)bnr * lda + k] : 0.f;
        }
        __syncthreads();
#pragma unroll
        for (int kk = 0; kk < TBK; kk++) {
            float4 a4 = *reinterpret_cast<const float4*>(&As[kk][ty * 4]);
            float4 b4 = *reinterpret_cast<const float4*>(&Bs[kk][tx * 4]);
            float ar[4] = {a4.x, a4.y, a4.z, a4.w};
            float br[4] = {b4.x, b4.y, b4.z, b4.w};
#pragma unroll
            for (int i = 0; i < 4; i++)
#pragma unroll
                for (int j = 0; j < 4; j++) {
                    float d = __fsub_rn(ar[i], br[j]);
                    acc[i][j] = fmaf(d, d, acc[i][j]);
                }
        }
        __syncthreads();
    }

#pragma unroll
    for (int i = 0; i < 4; i++) {
        int m = bm + ty * 4 + i;
        if (m >= N) continue;
#pragma unroll
        for (int j = 0; j < 4; j++) {
            int n = bn + tx * 4 + j;
            if (n >= N) continue;
            D[(size_t)m * ldc + n] = acc[i][j];
        }
    }
}

// ---------------- generic NT SGEMM (exact fp32, ascending FFMA chain) ------
#define EPI_AFF        1
#define EPI_AFF_LRELU  2

template <int EPI>
__global__ void __launch_bounds__(256) sgemm_nt(
    const float* __restrict__ A, int lda,
    const float* __restrict__ B, int ldb,
    float* __restrict__ C, int ldc,
    int M, int N, int Kd,
    const float* __restrict__ gv, const float* __restrict__ bv)
{
    __shared__ __align__(16) float As[TBK][TBM];
    __shared__ __align__(16) float Bs[TBK][TBN];

    int tid = threadIdx.x;
    int bm = blockIdx.y * TBM;
    int bn = blockIdx.x * TBN;
    int tx = tid & 15;
    int ty = tid >> 4;
    int lr = tid >> 2;
    int lk = (tid & 3) * 4;

    float acc[4][4];
#pragma unroll
    for (int i = 0; i < 4; i++)
#pragma unroll
        for (int j = 0; j < 4; j++) acc[i][j] = 0.f;

    int am  = bm + lr;
    int bnr = bn + lr;

    for (int k0 = 0; k0 < Kd; k0 += TBK) {
#pragma unroll
        for (int i = 0; i < 4; i++) {
            int k = k0 + lk + i;
            As[lk + i][lr] = (am  < M && k < Kd) ? A[(size_t)am  * lda + k] : 0.f;
            Bs[lk + i][lr] = (bnr < N && k < Kd) ? B[(size_t)bnr * ldb + k] : 0.f;
        }
        __syncthreads();
#pragma unroll
        for (int kk = 0; kk < TBK; kk++) {
            float4 a4 = *reinterpret_cast<const float4*>(&As[kk][ty * 4]);
            float4 b4 = *reinterpret_cast<const float4*>(&Bs[kk][tx * 4]);
            float ar[4] = {a4.x, a4.y, a4.z, a4.w};
            float br[4] = {b4.x, b4.y, b4.z, b4.w};
#pragma unroll
            for (int i = 0; i < 4; i++)
#pragma unroll
                for (int j = 0; j < 4; j++)
                    acc[i][j] = fmaf(ar[i], br[j], acc[i][j]);
        }
        __syncthreads();
    }

#pragma unroll
    for (int i = 0; i < 4; i++) {
        int m = bm + ty * 4 + i;
        if (m >= M) continue;
#pragma unroll
        for (int j = 0; j < 4; j++) {
            int n = bn + tx * 4 + j;
            if (n >= N) continue;
            float v = acc[i][j];
            float gg = gv ? gv[n] : 1.f;
            float bb = bv ? bv[n] : 0.f;
            v = __fadd_rn(__fmul_rn(v, gg), bb);
            if (EPI == EPI_AFF_LRELU)
                v = (v >= 0.f) ? v : __fmul_rn(0.2f, v);
            C[(size_t)m * ldc + n] = v;
        }
    }
}

// ---------------- helpers ---------------------------------------------------
__global__ void concat_kernel(const float* __restrict__ pts,
                              const float* __restrict__ feat,
                              float* __restrict__ X0, int N)
{
    int n = blockIdx.x * blockDim.x + threadIdx.x;
    if (n >= N) return;
    X0[n * 4 + 0] = pts[n * 3 + 0];
    X0[n * 4 + 1] = pts[n * 3 + 1];
    X0[n * 4 + 2] = pts[n * 3 + 2];
    X0[n * 4 + 3] = feat[n];
}

// ---------------- warp-per-row top-k with shared prune threshold -----------
__global__ void __launch_bounds__(256) topk_kernel(
    const float* __restrict__ D, int N, int* __restrict__ out)
{
    int warp = threadIdx.x >> 5;
    int lane = threadIdx.x & 31;
    int row  = blockIdx.x * 8 + warp;
    if (row >= N) return;
    const float* drow = D + (size_t)row * N;

    float ld[KNN];
    int   li[KNN];
#pragma unroll
    for (int t = 0; t < KNN; t++) { ld[t] = FLT_MAX; li[t] = 0x7FFFFFFF; }
    float wd = FLT_MAX;
    int   wi = 0x7FFFFFFF;
    int   ws = 0;
    float T  = FLT_MAX;

    int iters = (N + 31) >> 5;
    for (int it = 0; it < iters; it++) {
        int j = it * 32 + lane;
        float d = (j < N) ? drow[j] : FLT_MAX;
        bool better = (j < N) && (d <= T) &&
                      ((d < wd) || (d == wd && j < wi));
        if (better) {
#pragma unroll
            for (int t = 0; t < KNN; t++)
                if (t == ws) { ld[t] = d; li[t] = j; }
            wd = ld[0]; wi = li[0]; ws = 0;
#pragma unroll
            for (int t = 1; t < KNN; t++) {
                bool worse = (ld[t] > wd) || (ld[t] == wd && li[t] > wi);
                if (worse) { wd = ld[t]; wi = li[t]; ws = t; }
            }
        }
        if (__any_sync(0xffffffffu, better)) {
            float tmin = wd;
#pragma unroll
            for (int off = 16; off > 0; off >>= 1)
                tmin = fminf(tmin, __shfl_xor_sync(0xffffffffu, tmin, off));
            T = tmin;
        }
    }

    for (int s = 0; s < KNN; s++) {
        float md = ld[0]; int mi = li[0]; int ms = 0;
#pragma unroll
        for (int t = 1; t < KNN; t++) {
            bool b = (ld[t] < md) || (ld[t] == md && li[t] < mi);
            if (b) { md = ld[t]; mi = li[t]; ms = t; }
        }
        float bd = md; int bi = mi;
#pragma unroll
        for (int off = 16; off > 0; off >>= 1) {
            float od = __shfl_down_sync(0xffffffffu, bd, off);
            int   oi = __shfl_down_sync(0xffffffffu, bi, off);
            if (od < bd || (od == bd && oi < bi)) { bd = od; bi = oi; }
        }
        bd = __shfl_sync(0xffffffffu, bd, 0);
        bi = __shfl_sync(0xffffffffu, bi, 0);
        if (bi == mi) {
#pragma unroll
            for (int t = 0; t < KNN; t++)
                if (t == ms) { ld[t] = FLT_MAX; li[t] = 0x7FFFFFFF; }
        }
        if (lane == 0) out[row * KNN + s] = bi;
    }
}

// ---------------- fused edge conv (exact fp32) -----------------------------
// f = [x_j - x_i (rounded sub), x_i]; y = single ascending fma chain over 2C
// (diff channels first, then center channels).
template <int C>
__global__ void __launch_bounds__(256) edge_conv_kernel(
    const float* __restrict__ X, int lda,
    const float* __restrict__ w,      // [64, 2C]
    const int* __restrict__ idx,
    const float* __restrict__ g, const float* __restrict__ b,
    float* __restrict__ out, int colofs, int N)
{
    __shared__ float ws[2 * C][64];
    __shared__ float xs[4][C];
    __shared__ float ds[4][C];

    int tid = threadIdx.x;
    int o = tid & 63;
    int r = tid >> 6;
    int n = blockIdx.x * 4 + r;
    bool active = (n < N);

    for (int e = tid; e < 2 * C * 64; e += 256) {
        int oo = e / (2 * C), cc = e % (2 * C);
        ws[cc][oo] = w[oo * 2 * C + cc];
    }
    if (active) {
        for (int c = o; c < C; c += 64)
            xs[r][c] = X[(size_t)n * lda + c];
    }
    __syncthreads();

    float gg = active ? g[o] : 0.f;
    float bb = active ? b[o] : 0.f;
    float m = -FLT_MAX;
    const int* row = idx + (size_t)(active ? n : 0) * KNN;

    for (int k = 0; k < KNN; k++) {
        int j = active ? row[k] : 0;
        if (active && o < C)
            ds[r][o] = __fsub_rn(X[(size_t)j * lda + o], xs[r][o]);
        __syncthreads();
        if (active) {
            float y = 0.f;
#pragma unroll
            for (int c = 0; c < C; c++)
                y = fmaf(ds[r][c], ws[c][o], y);
#pragma unroll
            for (int c = 0; c < C; c++)
                y = fmaf(xs[r][c], ws[C + c][o], y);
            float z = __fadd_rn(__fmul_rn(y, gg), bb);
            z = (z >= 0.f) ? z : __fmul_rn(0.2f, z);
            m = fmaxf(m, z);
        }
        __syncthreads();
    }
    if (active)
        out[(size_t)n * 256 + colofs + o] = m;
}

// ---------------- launch ----------------------------------------------------
extern "C" void kernel_launch(void* const* d_in, const int* in_sizes, int n_in,
                              void* d_out, int out_size)
{
    const float* pts   = (const float*)d_in[0];
    const float* feats = (const float*)d_in[1];
    const float* W[4]  = { (const float*)d_in[2], (const float*)d_in[5],
                           (const float*)d_in[8], (const float*)d_in[11] };
    const float* G[4]  = { (const float*)d_in[3], (const float*)d_in[6],
                           (const float*)d_in[9], (const float*)d_in[12] };
    const float* Bv[4] = { (const float*)d_in[4], (const float*)d_in[7],
                           (const float*)d_in[10], (const float*)d_in[13] };
    const float* w5 = (const float*)d_in[14];
    const float* g5 = (const float*)d_in[15];
    const float* b5 = (const float*)d_in[16];
    const float* wf = (const float*)d_in[17];
    const float* go = (const float*)d_in[18];
    const float* bo = (const float*)d_in[19];
    const float* wh = (const float*)d_in[20];
    const float* bh = (const float*)d_in[21];
    float* outp = (float*)d_out;

    int N = in_sizes[0] / 3;   // 12000

    float *pD, *pX0, *pX14, *pY5, *pF;
    int *pidx;
    cudaGetSymbolAddress((void**)&pD,   g_D);
    cudaGetSymbolAddress((void**)&pidx, g_idx);
    cudaGetSymbolAddress((void**)&pX0,  g_X0);
    cudaGetSymbolAddress((void**)&pX14, g_X14);
    cudaGetSymbolAddress((void**)&pY5,  g_Y5);
    cudaGetSymbolAddress((void**)&pF,   g_F);

    int nb256 = (N + 255) / 256;
    int nb4   = (N + 3) / 4;
    int nb8   = (N + 7) / 8;
    dim3 gDist((N + 63) / 64, (N + 63) / 64);

    concat_kernel<<<nb256, 256>>>(pts, feats, pX0, N);

    for (int blk = 0; blk < 4; blk++) {
        const float* Xin;
        int lda, C;
        if (blk == 0) { Xin = pX0;                   lda = 4;   C = 4;  }
        else          { Xin = pX14 + (blk - 1) * 64; lda = 256; C = 64; }

        sqdist_nt<<<gDist, 256>>>(Xin, lda, pD, N, N, C);
        topk_kernel<<<nb8, 256>>>(pD, N, pidx);
        if (blk == 0)
            edge_conv_kernel<4><<<nb4, 256>>>(Xin, lda, W[blk], pidx,
                                              G[blk], Bv[blk], pX14, 0, N);
        else
            edge_conv_kernel<64><<<nb4, 256>>>(Xin, lda, W[blk], pidx,
                                               G[blk], Bv[blk], pX14,
                                               blk * 64, N);
    }

    // conv5: [N,256] x [1024,256]^T -> lrelu(.*g5+b5) -> [N,1024]
    sgemm_nt<EPI_AFF_LRELU><<<dim3((1024 + 63) / 64, (N + 63) / 64), 256>>>(
        pX14, 256, w5, 256, pY5, 1024, N, 1024, 256, g5, b5);
    // feat: [N,1024] x [256,1024]^T -> .*go+bo -> [N,256]
    sgemm_nt<EPI_AFF><<<dim3((256 + 63) / 64, (N + 63) / 64), 256>>>(
        pY5, 1024, wf, 1024, pF, 256, N, 256, 1024, go, bo);
    // head: [N,256] x [20,256]^T + bh -> [N,20]
    sgemm_nt<EPI_AFF><<<dim3(1, (N + 63) / 64), 256>>>(
        pF, 256, wh, 256, outp, 20, N, 20, 256, nullptr, bh);
}

// round 8
// speedup vs baseline: 1.0630x; 1.0630x over previous
#include <cuda_runtime.h>
#include <float.h>
#include <stdint.h>

#define MAXN 12000
#define KNN  20

// ---------------- scratch (static device globals; no runtime allocation) ---
__device__ float g_D[(size_t)MAXN * MAXN];      // 576 MB distance matrix (reused)
__device__ int   g_idx[MAXN * KNN];
__device__ float g_X0[MAXN * 4];
__device__ float g_X14[MAXN * 256];             // x1|x2|x3|x4 concatenated
__device__ float g_Y5[(size_t)MAXN * 1024];
__device__ float g_F[MAXN * 256];

// ---------------- pairwise squared distances, 128x128x16, 8x8/thread -------
// D[m,n] = sum_c (A[m,c]-A[n,c])^2 ; per-output single ascending-c chain of
// FSUB+FFMA — bit-identical to the round-6 passing kernel.
#define TM 128
#define TN 128
#define TK 16
#define SSTR 132   // smem row stride in floats (16B-aligned, conflict-free)

__global__ void __launch_bounds__(256) sqdist128(
    const float* __restrict__ A, int lda,
    float* __restrict__ D, int ldc,
    int N, int Kd)
{
    __shared__ __align__(16) float As[TK][SSTR];
    __shared__ __align__(16) float Bs[TK][SSTR];

    int tid = threadIdx.x;
    int bm = blockIdx.y * TM;
    int bn = blockIdx.x * TN;
    int tx = tid & 15;           // 0..15
    int ty = tid >> 4;           // 0..15
    int r  = tid & 127;          // loader row within tile
    int kq = tid >> 7;           // loader k-half (0/1)

    bool arow_ok = (bm + r) < N;
    bool brow_ok = (bn + r) < N;
    const float* Arow = A + (size_t)(bm + r) * lda;
    const float* Brow = A + (size_t)(bn + r) * lda;

    float acc[8][8];
#pragma unroll
    for (int i = 0; i < 8; i++)
#pragma unroll
        for (int j = 0; j < 8; j++) acc[i][j] = 0.f;

    for (int k0 = 0; k0 < Kd; k0 += TK) {
#pragma unroll
        for (int i = 0; i < 8; i++) {
            int k  = kq * 8 + i;
            int kg = k0 + k;
            bool kok = kg < Kd;
            As[k][r] = (arow_ok && kok) ? Arow[kg] : 0.f;
            Bs[k][r] = (brow_ok && kok) ? Brow[kg] : 0.f;
        }
        __syncthreads();
#pragma unroll
        for (int kk = 0; kk < TK; kk++) {
            float4 a0 = *reinterpret_cast<const float4*>(&As[kk][ty * 4]);
            float4 a1 = *reinterpret_cast<const float4*>(&As[kk][ty * 4 + 64]);
            float4 b0 = *reinterpret_cast<const float4*>(&Bs[kk][tx * 4]);
            float4 b1 = *reinterpret_cast<const float4*>(&Bs[kk][tx * 4 + 64]);
            float ar[8] = {a0.x, a0.y, a0.z, a0.w, a1.x, a1.y, a1.z, a1.w};
            float br[8] = {b0.x, b0.y, b0.z, b0.w, b1.x, b1.y, b1.z, b1.w};
#pragma unroll
            for (int i = 0; i < 8; i++)
#pragma unroll
                for (int j = 0; j < 8; j++) {
                    float d = __fsub_rn(ar[i], br[j]);
                    acc[i][j] = fmaf(d, d, acc[i][j]);
                }
        }
        __syncthreads();
    }

#pragma unroll
    for (int i = 0; i < 8; i++) {
        int m = bm + ((i < 4) ? (ty * 4 + i) : (64 + ty * 4 + i - 4));
        if (m >= N) continue;
        float* drow = D + (size_t)m * ldc;
#pragma unroll
        for (int cq = 0; cq < 2; cq++) {
            int n = bn + cq * 64 + tx * 4;
            if (n + 3 < N) {
                float4 v = make_float4(acc[i][cq*4+0], acc[i][cq*4+1],
                                       acc[i][cq*4+2], acc[i][cq*4+3]);
                *reinterpret_cast<float4*>(&drow[n]) = v;
            } else {
#pragma unroll
                for (int j = 0; j < 4; j++)
                    if (n + j < N) drow[n + j] = acc[i][cq*4+j];
            }
        }
    }
}

// ---------------- generic NT SGEMM (exact fp32, ascending FFMA chain) ------
#define TBM 64
#define TBN 64
#define TBK 16

#define EPI_AFF        1
#define EPI_AFF_LRELU  2

template <int EPI>
__global__ void __launch_bounds__(256) sgemm_nt(
    const float* __restrict__ A, int lda,
    const float* __restrict__ B, int ldb,
    float* __restrict__ C, int ldc,
    int M, int N, int Kd,
    const float* __restrict__ gv, const float* __restrict__ bv)
{
    __shared__ __align__(16) float As[TBK][TBM];
    __shared__ __align__(16) float Bs[TBK][TBN];

    int tid = threadIdx.x;
    int bm = blockIdx.y * TBM;
    int bn = blockIdx.x * TBN;
    int tx = tid & 15;
    int ty = tid >> 4;
    int lr = tid >> 2;
    int lk = (tid & 3) * 4;

    float acc[4][4];
#pragma unroll
    for (int i = 0; i < 4; i++)
#pragma unroll
        for (int j = 0; j < 4; j++) acc[i][j] = 0.f;

    int am  = bm + lr;
    int bnr = bn + lr;

    for (int k0 = 0; k0 < Kd; k0 += TBK) {
#pragma unroll
        for (int i = 0; i < 4; i++) {
            int k = k0 + lk + i;
            As[lk + i][lr] = (am  < M && k < Kd) ? A[(size_t)am  * lda + k] : 0.f;
            Bs[lk + i][lr] = (bnr < N && k < Kd) ? B[(size_t)bnr * ldb + k] : 0.f;
        }
        __syncthreads();
#pragma unroll
        for (int kk = 0; kk < TBK; kk++) {
            float4 a4 = *reinterpret_cast<const float4*>(&As[kk][ty * 4]);
            float4 b4 = *reinterpret_cast<const float4*>(&Bs[kk][tx * 4]);
            float ar[4] = {a4.x, a4.y, a4.z, a4.w};
            float br[4] = {b4.x, b4.y, b4.z, b4.w};
#pragma unroll
            for (int i = 0; i < 4; i++)
#pragma unroll
                for (int j = 0; j < 4; j++)
                    acc[i][j] = fmaf(ar[i], br[j], acc[i][j]);
        }
        __syncthreads();
    }

#pragma unroll
    for (int i = 0; i < 4; i++) {
        int m = bm + ty * 4 + i;
        if (m >= M) continue;
#pragma unroll
        for (int j = 0; j < 4; j++) {
            int n = bn + tx * 4 + j;
            if (n >= N) continue;
            float v = acc[i][j];
            float gg = gv ? gv[n] : 1.f;
            float bb = bv ? bv[n] : 0.f;
            v = __fadd_rn(__fmul_rn(v, gg), bb);
            if (EPI == EPI_AFF_LRELU)
                v = (v >= 0.f) ? v : __fmul_rn(0.2f, v);
            C[(size_t)m * ldc + n] = v;
        }
    }
}

// ---------------- helpers ---------------------------------------------------
__global__ void concat_kernel(const float* __restrict__ pts,
                              const float* __restrict__ feat,
                              float* __restrict__ X0, int N)
{
    int n = blockIdx.x * blockDim.x + threadIdx.x;
    if (n >= N) return;
    X0[n * 4 + 0] = pts[n * 3 + 0];
    X0[n * 4 + 1] = pts[n * 3 + 1];
    X0[n * 4 + 2] = pts[n * 3 + 2];
    X0[n * 4 + 3] = feat[n];
}

// ---------------- warp-per-row top-k, float4 scan + shared prune threshold -
__global__ void __launch_bounds__(256) topk_kernel(
    const float* __restrict__ D, int N, int* __restrict__ out)
{
    int warp = threadIdx.x >> 5;
    int lane = threadIdx.x & 31;
    int row  = blockIdx.x * 8 + warp;
    if (row >= N) return;
    const float4* drow4 = reinterpret_cast<const float4*>(D + (size_t)row * N);
    int n4 = N >> 2;                 // N divisible by 4 (12000)

    float ld[KNN];
    int   li[KNN];
#pragma unroll
    for (int t = 0; t < KNN; t++) { ld[t] = FLT_MAX; li[t] = 0x7FFFFFFF; }
    float wd = FLT_MAX;
    int   wi = 0x7FFFFFFF;
    int   ws = 0;
    float T  = FLT_MAX;

    int iters = (n4 + 31) >> 5;
    for (int it = 0; it < iters; it++) {
        int i4 = it * 32 + lane;
        bool valid = (i4 < n4);
        float4 v = valid ? drow4[i4]
                         : make_float4(FLT_MAX, FLT_MAX, FLT_MAX, FLT_MAX);
        int jb = i4 * 4;
        bool changed = false;
#pragma unroll
        for (int e = 0; e < 4; e++) {
            float d = (e == 0) ? v.x : (e == 1) ? v.y : (e == 2) ? v.z : v.w;
            int   j = jb + e;
            bool better = valid && (d <= T) &&
                          ((d < wd) || (d == wd && j < wi));
            if (better) {
#pragma unroll
                for (int t = 0; t < KNN; t++)
                    if (t == ws) { ld[t] = d; li[t] = j; }
                wd = ld[0]; wi = li[0]; ws = 0;
#pragma unroll
                for (int t = 1; t < KNN; t++) {
                    bool worse = (ld[t] > wd) || (ld[t] == wd && li[t] > wi);
                    if (worse) { wd = ld[t]; wi = li[t]; ws = t; }
                }
                changed = true;
            }
        }
        if (__any_sync(0xffffffffu, changed)) {
            float tmin = wd;
#pragma unroll
            for (int off = 16; off > 0; off >>= 1)
                tmin = fminf(tmin, __shfl_xor_sync(0xffffffffu, tmin, off));
            T = tmin;
        }
    }

    // merge: 20 rounds of warp-wide lexicographic arg-min extraction
    for (int s = 0; s < KNN; s++) {
        float md = ld[0]; int mi = li[0]; int ms = 0;
#pragma unroll
        for (int t = 1; t < KNN; t++) {
            bool b = (ld[t] < md) || (ld[t] == md && li[t] < mi);
            if (b) { md = ld[t]; mi = li[t]; ms = t; }
        }
        float bd = md; int bi = mi;
#pragma unroll
        for (int off = 16; off > 0; off >>= 1) {
            float od = __shfl_down_sync(0xffffffffu, bd, off);
            int   oi = __shfl_down_sync(0xffffffffu, bi, off);
            if (od < bd || (od == bd && oi < bi)) { bd = od; bi = oi; }
        }
        bd = __shfl_sync(0xffffffffu, bd, 0);
        bi = __shfl_sync(0xffffffffu, bi, 0);
        if (bi == mi) {
#pragma unroll
            for (int t = 0; t < KNN; t++)
                if (t == ms) { ld[t] = FLT_MAX; li[t] = 0x7FFFFFFF; }
        }
        if (lane == 0) out[row * KNN + s] = bi;
    }
}

// ---------------- fused edge conv (exact fp32) -----------------------------
template <int C>
__global__ void __launch_bounds__(256) edge_conv_kernel(
    const float* __restrict__ X, int lda,
    const float* __restrict__ w,      // [64, 2C]
    const int* __restrict__ idx,
    const float* __restrict__ g, const float* __restrict__ b,
    float* __restrict__ out, int colofs, int N)
{
    __shared__ float ws[2 * C][64];
    __shared__ float xs[4][C];
    __shared__ float ds[4][C];

    int tid = threadIdx.x;
    int o = tid & 63;
    int r = tid >> 6;
    int n = blockIdx.x * 4 + r;
    bool active = (n < N);

    for (int e = tid; e < 2 * C * 64; e += 256) {
        int oo = e / (2 * C), cc = e % (2 * C);
        ws[cc][oo] = w[oo * 2 * C + cc];
    }
    if (active) {
        for (int c = o; c < C; c += 64)
            xs[r][c] = X[(size_t)n * lda + c];
    }
    __syncthreads();

    float gg = active ? g[o] : 0.f;
    float bb = active ? b[o] : 0.f;
    float m = -FLT_MAX;
    const int* row = idx + (size_t)(active ? n : 0) * KNN;

    for (int k = 0; k < KNN; k++) {
        int j = active ? row[k] : 0;
        if (active && o < C)
            ds[r][o] = __fsub_rn(X[(size_t)j * lda + o], xs[r][o]);
        __syncthreads();
        if (active) {
            float y = 0.f;
#pragma unroll
            for (int c = 0; c < C; c++)
                y = fmaf(ds[r][c], ws[c][o], y);
#pragma unroll
            for (int c = 0; c < C; c++)
                y = fmaf(xs[r][c], ws[C + c][o], y);
            float z = __fadd_rn(__fmul_rn(y, gg), bb);
            z = (z >= 0.f) ? z : __fmul_rn(0.2f, z);
            m = fmaxf(m, z);
        }
        __syncthreads();
    }
    if (active)
        out[(size_t)n * 256 + colofs + o] = m;
}

// ---------------- launch ----------------------------------------------------
extern "C" void kernel_launch(void* const* d_in, const int* in_sizes, int n_in,
                              void* d_out, int out_size)
{
    const float* pts   = (const float*)d_in[0];
    const float* feats = (const float*)d_in[1];
    const float* W[4]  = { (const float*)d_in[2], (const float*)d_in[5],
                           (const float*)d_in[8], (const float*)d_in[11] };
    const float* G[4]  = { (const float*)d_in[3], (const float*)d_in[6],
                           (const float*)d_in[9], (const float*)d_in[12] };
    const float* Bv[4] = { (const float*)d_in[4], (const float*)d_in[7],
                           (const float*)d_in[10], (const float*)d_in[13] };
    const float* w5 = (const float*)d_in[14];
    const float* g5 = (const float*)d_in[15];
    const float* b5 = (const float*)d_in[16];
    const float* wf = (const float*)d_in[17];
    const float* go = (const float*)d_in[18];
    const float* bo = (const float*)d_in[19];
    const float* wh = (const float*)d_in[20];
    const float* bh = (const float*)d_in[21];
    float* outp = (float*)d_out;

    int N = in_sizes[0] / 3;   // 12000

    float *pD, *pX0, *pX14, *pY5, *pF;
    int *pidx;
    cudaGetSymbolAddress((void**)&pD,   g_D);
    cudaGetSymbolAddress((void**)&pidx, g_idx);
    cudaGetSymbolAddress((void**)&pX0,  g_X0);
    cudaGetSymbolAddress((void**)&pX14, g_X14);
    cudaGetSymbolAddress((void**)&pY5,  g_Y5);
    cudaGetSymbolAddress((void**)&pF,   g_F);

    int nb256 = (N + 255) / 256;
    int nb4   = (N + 3) / 4;
    int nb8   = (N + 7) / 8;
    dim3 gDist((N + TN - 1) / TN, (N + TM - 1) / TM);

    concat_kernel<<<nb256, 256>>>(pts, feats, pX0, N);

    for (int blk = 0; blk < 4; blk++) {
        const float* Xin;
        int lda, C;
        if (blk == 0) { Xin = pX0;                   lda = 4;   C = 4;  }
        else          { Xin = pX14 + (blk - 1) * 64; lda = 256; C = 64; }

        sqdist128<<<gDist, 256>>>(Xin, lda, pD, N, N, C);
        topk_kernel<<<nb8, 256>>>(pD, N, pidx);
        if (blk == 0)
            edge_conv_kernel<4><<<nb4, 256>>>(Xin, lda, W[blk], pidx,
                                              G[blk], Bv[blk], pX14, 0, N);
        else
            edge_conv_kernel<64><<<nb4, 256>>>(Xin, lda, W[blk], pidx,
                                               G[blk], Bv[blk], pX14,
                                               blk * 64, N);
    }

    // conv5: [N,256] x [1024,256]^T -> lrelu(.*g5+b5) -> [N,1024]
    sgemm_nt<EPI_AFF_LRELU><<<dim3((1024 + 63) / 64, (N + 63) / 64), 256>>>(
        pX14, 256, w5, 256, pY5, 1024, N, 1024, 256, g5, b5);
    // feat: [N,1024] x [256,1024]^T -> .*go+bo -> [N,256]
    sgemm_nt<EPI_AFF><<<dim3((256 + 63) / 64, (N + 63) / 64), 256>>>(
        pY5, 1024, wf, 1024, pF, 256, N, 256, 1024, go, bo);
    // head: [N,256] x [20,256]^T + bh -> [N,20]
    sgemm_nt<EPI_AFF><<<dim3(1, (N + 63) / 64), 256>>>(
        pF, 256, wh, 256, outp, 20, N, 20, 256, nullptr, bh);
}

// round 9
// speedup vs baseline: 1.2393x; 1.1658x over previous
#include <cuda_runtime.h>
#include <float.h>
#include <stdint.h>

#define MAXN 12000
#define KNN  20

typedef unsigned long long ull;

// ---------------- scratch (static device globals; no runtime allocation) ---
__device__ float g_D[(size_t)MAXN * MAXN];      // 576 MB distance matrix (reused)
__device__ int   g_idx[MAXN * KNN];
__device__ float g_X0[MAXN * 4];
__device__ float g_Xt[(size_t)64 * MAXN];       // transposed feature panel
__device__ float g_X14[MAXN * 256];             // x1|x2|x3|x4 concatenated
__device__ float g_Y5[(size_t)MAXN * 1024];
__device__ float g_F[MAXN * 256];

// ---------------- f32x2 packed helpers (sm_100a) ---------------------------
__device__ __forceinline__ ull pack_dup(float x) {
    ull r;
    asm("mov.b64 %0, {%1, %1};" : "=l"(r) : "f"(x));
    return r;
}
__device__ __forceinline__ ull add2(ull a, ull b) {
    ull r;
    asm("add.rn.f32x2 %0, %1, %2;" : "=l"(r) : "l"(a), "l"(b));
    return r;
}
__device__ __forceinline__ ull fma2(ull a, ull b, ull c) {
    ull r;
    asm("fma.rn.f32x2 %0, %1, %2, %3;" : "=l"(r) : "l"(a), "l"(b), "l"(c));
    return r;
}
__device__ __forceinline__ void unpack2(ull v, float& lo, float& hi) {
    asm("mov.b64 {%0, %1}, %2;" : "=f"(lo), "=f"(hi) : "l"(v));
}

// ---------------- transpose: Xt[c][n] = X[n][c] ----------------------------
__global__ void transpose_kernel(const float* __restrict__ X, int lda, int C,
                                 float* __restrict__ Xt, int N)
{
    int n = blockIdx.x * blockDim.x + threadIdx.x;
    int c = blockIdx.y;
    if (n < N && c < C)
        Xt[(size_t)c * N + n] = X[(size_t)n * lda + c];
}

// ---------------- pairwise squared distances, 128x128, f32x2 packed --------
// D[m,n] = sum_c (A[m,c]-A[n,c])^2 computed as fma2(d,d,acc), d = a + (-b).
// Per-output single ascending-c chain, each half IEEE fp32 — bit-identical
// to the scalar FSUB+FFMA version.
#define TM 128
#define TN 128
#define SSTR 132

template <int TKK>
__global__ void __launch_bounds__(256) sqdist_f2(
    const float* __restrict__ Xt,
    float* __restrict__ D, int N, int Kd)
{
    __shared__ __align__(16) float As[TKK][SSTR];
    __shared__ __align__(16) float Bs[TKK][SSTR];   // stores NEGATED values

    int tid = threadIdx.x;
    int bm = blockIdx.y * TM;
    int bn = blockIdx.x * TN;
    int tx = tid & 15;
    int ty = tid >> 4;
    int w  = tid >> 5;
    int l  = tid & 31;

    ull acc2[8][4];
#pragma unroll
    for (int i = 0; i < 8; i++)
#pragma unroll
        for (int j = 0; j < 4; j++) acc2[i][j] = 0ULL;

    for (int k0 = 0; k0 < Kd; k0 += TKK) {
        // load panels: warp handles whole k-rows; lanes along n -> coalesced
#pragma unroll
        for (int t = w; t < 2 * TKK; t += 8) {
            bool isB = (t >= TKK);
            int k = isB ? (t - TKK) : t;
            int kg = k0 + k;
            int base = (isB ? bn : bm) + l * 4;
            float4 v = make_float4(0.f, 0.f, 0.f, 0.f);
            if (kg < Kd) {
                const float* src = Xt + (size_t)kg * N;
                if (base + 3 < N) v = *reinterpret_cast<const float4*>(&src[base]);
                else {
                    if (base + 0 < N) v.x = src[base + 0];
                    if (base + 1 < N) v.y = src[base + 1];
                    if (base + 2 < N) v.z = src[base + 2];
                    if (base + 3 < N) v.w = src[base + 3];
                }
            }
            if (isB) {
                Bs[k][l * 4 + 0] = -v.x;
                Bs[k][l * 4 + 1] = -v.y;
                Bs[k][l * 4 + 2] = -v.z;
                Bs[k][l * 4 + 3] = -v.w;
            } else {
                *reinterpret_cast<float4*>(&As[k][l * 4]) = v;
            }
        }
        __syncthreads();

#pragma unroll
        for (int kk = 0; kk < TKK; kk++) {
            float4 a0 = *reinterpret_cast<const float4*>(&As[kk][ty * 4]);
            float4 a1 = *reinterpret_cast<const float4*>(&As[kk][ty * 4 + 64]);
            ulonglong2 b0 = *reinterpret_cast<const ulonglong2*>(&Bs[kk][tx * 4]);
            ulonglong2 b1 = *reinterpret_cast<const ulonglong2*>(&Bs[kk][tx * 4 + 64]);
            ull br2[4] = { b0.x, b0.y, b1.x, b1.y };
            float ar[8] = { a0.x, a0.y, a0.z, a0.w, a1.x, a1.y, a1.z, a1.w };
#pragma unroll
            for (int i = 0; i < 8; i++) {
                ull a2 = pack_dup(ar[i]);
#pragma unroll
                for (int jj = 0; jj < 4; jj++) {
                    ull d2 = add2(a2, br2[jj]);   // a + (-b)
                    acc2[i][jj] = fma2(d2, d2, acc2[i][jj]);
                }
            }
        }
        __syncthreads();
    }

#pragma unroll
    for (int i = 0; i < 8; i++) {
        int m = bm + ((i < 4) ? (ty * 4 + i) : (64 + ty * 4 + i - 4));
        if (m >= N) continue;
        float* drow = D + (size_t)m * N;
#pragma unroll
        for (int cq = 0; cq < 2; cq++) {
            float c0, c1, c2, c3;
            unpack2(acc2[i][cq * 2 + 0], c0, c1);
            unpack2(acc2[i][cq * 2 + 1], c2, c3);
            int n = bn + cq * 64 + tx * 4;
            if (n + 3 < N) {
                *reinterpret_cast<float4*>(&drow[n]) = make_float4(c0, c1, c2, c3);
            } else {
                if (n + 0 < N) drow[n + 0] = c0;
                if (n + 1 < N) drow[n + 1] = c1;
                if (n + 2 < N) drow[n + 2] = c2;
                if (n + 3 < N) drow[n + 3] = c3;
            }
        }
    }
}

// ---------------- generic NT SGEMM (f32x2 packed, exact ascending chains) --
#define TBM 64
#define TBN 64
#define TBK 16

#define EPI_AFF        1
#define EPI_AFF_LRELU  2

template <int EPI>
__global__ void __launch_bounds__(256) sgemm_nt(
    const float* __restrict__ A, int lda,
    const float* __restrict__ B, int ldb,
    float* __restrict__ C, int ldc,
    int M, int N, int Kd,
    const float* __restrict__ gv, const float* __restrict__ bv)
{
    __shared__ __align__(16) float As[TBK][TBM];
    __shared__ __align__(16) float Bs[TBK][TBN];

    int tid = threadIdx.x;
    int bm = blockIdx.y * TBM;
    int bn = blockIdx.x * TBN;
    int tx = tid & 15;
    int ty = tid >> 4;
    int lr = tid >> 2;
    int lk = (tid & 3) * 4;

    ull acc2[4][2];
#pragma unroll
    for (int i = 0; i < 4; i++) { acc2[i][0] = 0ULL; acc2[i][1] = 0ULL; }

    int am  = bm + lr;
    int bnr = bn + lr;

    for (int k0 = 0; k0 < Kd; k0 += TBK) {
#pragma unroll
        for (int i = 0; i < 4; i++) {
            int k = k0 + lk + i;
            As[lk + i][lr] = (am  < M && k < Kd) ? A[(size_t)am  * lda + k] : 0.f;
            Bs[lk + i][lr] = (bnr < N && k < Kd) ? B[(size_t)bnr * ldb + k] : 0.f;
        }
        __syncthreads();
#pragma unroll
        for (int kk = 0; kk < TBK; kk++) {
            float4 a4 = *reinterpret_cast<const float4*>(&As[kk][ty * 4]);
            ulonglong2 bb = *reinterpret_cast<const ulonglong2*>(&Bs[kk][tx * 4]);
            float ar[4] = { a4.x, a4.y, a4.z, a4.w };
#pragma unroll
            for (int i = 0; i < 4; i++) {
                ull a2 = pack_dup(ar[i]);
                acc2[i][0] = fma2(a2, bb.x, acc2[i][0]);
                acc2[i][1] = fma2(a2, bb.y, acc2[i][1]);
            }
        }
        __syncthreads();
    }

#pragma unroll
    for (int i = 0; i < 4; i++) {
        int m = bm + ty * 4 + i;
        if (m >= M) continue;
        float c[4];
        unpack2(acc2[i][0], c[0], c[1]);
        unpack2(acc2[i][1], c[2], c[3]);
#pragma unroll
        for (int j = 0; j < 4; j++) {
            int n = bn + tx * 4 + j;
            if (n >= N) continue;
            float v = c[j];
            float gg = gv ? gv[n] : 1.f;
            float bb = bv ? bv[n] : 0.f;
            v = __fadd_rn(__fmul_rn(v, gg), bb);
            if (EPI == EPI_AFF_LRELU)
                v = (v >= 0.f) ? v : __fmul_rn(0.2f, v);
            C[(size_t)m * ldc + n] = v;
        }
    }
}

// ---------------- helpers ---------------------------------------------------
__global__ void concat_kernel(const float* __restrict__ pts,
                              const float* __restrict__ feat,
                              float* __restrict__ X0, int N)
{
    int n = blockIdx.x * blockDim.x + threadIdx.x;
    if (n >= N) return;
    X0[n * 4 + 0] = pts[n * 3 + 0];
    X0[n * 4 + 1] = pts[n * 3 + 1];
    X0[n * 4 + 2] = pts[n * 3 + 2];
    X0[n * 4 + 3] = feat[n];
}

// ---------------- warp-per-row top-k, float4 scan + shared prune threshold -
__global__ void __launch_bounds__(256) topk_kernel(
    const float* __restrict__ D, int N, int* __restrict__ out)
{
    int warp = threadIdx.x >> 5;
    int lane = threadIdx.x & 31;
    int row  = blockIdx.x * 8 + warp;
    if (row >= N) return;
    const float4* drow4 = reinterpret_cast<const float4*>(D + (size_t)row * N);
    int n4 = N >> 2;

    float ld[KNN];
    int   li[KNN];
#pragma unroll
    for (int t = 0; t < KNN; t++) { ld[t] = FLT_MAX; li[t] = 0x7FFFFFFF; }
    float wd = FLT_MAX;
    int   wi = 0x7FFFFFFF;
    int   ws = 0;
    float T  = FLT_MAX;

    int iters = (n4 + 31) >> 5;
    for (int it = 0; it < iters; it++) {
        int i4 = it * 32 + lane;
        bool valid = (i4 < n4);
        float4 v = valid ? drow4[i4]
                         : make_float4(FLT_MAX, FLT_MAX, FLT_MAX, FLT_MAX);
        int jb = i4 * 4;
        bool changed = false;
#pragma unroll
        for (int e = 0; e < 4; e++) {
            float d = (e == 0) ? v.x : (e == 1) ? v.y : (e == 2) ? v.z : v.w;
            int   j = jb + e;
            bool better = valid && (d <= T) &&
                          ((d < wd) || (d == wd && j < wi));
            if (better) {
#pragma unroll
                for (int t = 0; t < KNN; t++)
                    if (t == ws) { ld[t] = d; li[t] = j; }
                wd = ld[0]; wi = li[0]; ws = 0;
#pragma unroll
                for (int t = 1; t < KNN; t++) {
                    bool worse = (ld[t] > wd) || (ld[t] == wd && li[t] > wi);
                    if (worse) { wd = ld[t]; wi = li[t]; ws = t; }
                }
                changed = true;
            }
        }
        if (__any_sync(0xffffffffu, changed)) {
            float tmin = wd;
#pragma unroll
            for (int off = 16; off > 0; off >>= 1)
                tmin = fminf(tmin, __shfl_xor_sync(0xffffffffu, tmin, off));
            T = tmin;
        }
    }

    for (int s = 0; s < KNN; s++) {
        float md = ld[0]; int mi = li[0]; int ms = 0;
#pragma unroll
        for (int t = 1; t < KNN; t++) {
            bool b = (ld[t] < md) || (ld[t] == md && li[t] < mi);
            if (b) { md = ld[t]; mi = li[t]; ms = t; }
        }
        float bd = md; int bi = mi;
#pragma unroll
        for (int off = 16; off > 0; off >>= 1) {
            float od = __shfl_down_sync(0xffffffffu, bd, off);
            int   oi = __shfl_down_sync(0xffffffffu, bi, off);
            if (od < bd || (od == bd && oi < bi)) { bd = od; bi = oi; }
        }
        bd = __shfl_sync(0xffffffffu, bd, 0);
        bi = __shfl_sync(0xffffffffu, bi, 0);
        if (bi == mi) {
#pragma unroll
            for (int t = 0; t < KNN; t++)
                if (t == ms) { ld[t] = FLT_MAX; li[t] = 0x7FFFFFFF; }
        }
        if (lane == 0) out[row * KNN + s] = bi;
    }
}

// ---------------- fused edge conv (exact fp32) -----------------------------
template <int C>
__global__ void __launch_bounds__(256) edge_conv_kernel(
    const float* __restrict__ X, int lda,
    const float* __restrict__ w,      // [64, 2C]
    const int* __restrict__ idx,
    const float* __restrict__ g, const float* __restrict__ b,
    float* __restrict__ out, int colofs, int N)
{
    __shared__ float ws[2 * C][64];
    __shared__ float xs[4][C];
    __shared__ float ds[4][C];

    int tid = threadIdx.x;
    int o = tid & 63;
    int r = tid >> 6;
    int n = blockIdx.x * 4 + r;
    bool active = (n < N);

    for (int e = tid; e < 2 * C * 64; e += 256) {
        int oo = e / (2 * C), cc = e % (2 * C);
        ws[cc][oo] = w[oo * 2 * C + cc];
    }
    if (active) {
        for (int c = o; c < C; c += 64)
            xs[r][c] = X[(size_t)n * lda + c];
    }
    __syncthreads();

    float gg = active ? g[o] : 0.f;
    float bb = active ? b[o] : 0.f;
    float m = -FLT_MAX;
    const int* row = idx + (size_t)(active ? n : 0) * KNN;

    for (int k = 0; k < KNN; k++) {
        int j = active ? row[k] : 0;
        if (active && o < C)
            ds[r][o] = __fsub_rn(X[(size_t)j * lda + o], xs[r][o]);
        __syncthreads();
        if (active) {
            float y = 0.f;
#pragma unroll
            for (int c = 0; c < C; c++)
                y = fmaf(ds[r][c], ws[c][o], y);
#pragma unroll
            for (int c = 0; c < C; c++)
                y = fmaf(xs[r][c], ws[C + c][o], y);
            float z = __fadd_rn(__fmul_rn(y, gg), bb);
            z = (z >= 0.f) ? z : __fmul_rn(0.2f, z);
            m = fmaxf(m, z);
        }
        __syncthreads();
    }
    if (active)
        out[(size_t)n * 256 + colofs + o] = m;
}

// ---------------- launch ----------------------------------------------------
extern "C" void kernel_launch(void* const* d_in, const int* in_sizes, int n_in,
                              void* d_out, int out_size)
{
    const float* pts   = (const float*)d_in[0];
    const float* feats = (const float*)d_in[1];
    const float* W[4]  = { (const float*)d_in[2], (const float*)d_in[5],
                           (const float*)d_in[8], (const float*)d_in[11] };
    const float* G[4]  = { (const float*)d_in[3], (const float*)d_in[6],
                           (const float*)d_in[9], (const float*)d_in[12] };
    const float* Bv[4] = { (const float*)d_in[4], (const float*)d_in[7],
                           (const float*)d_in[10], (const float*)d_in[13] };
    const float* w5 = (const float*)d_in[14];
    const float* g5 = (const float*)d_in[15];
    const float* b5 = (const float*)d_in[16];
    const float* wf = (const float*)d_in[17];
    const float* go = (const float*)d_in[18];
    const float* bo = (const float*)d_in[19];
    const float* wh = (const float*)d_in[20];
    const float* bh = (const float*)d_in[21];
    float* outp = (float*)d_out;

    int N = in_sizes[0] / 3;   // 12000

    float *pD, *pX0, *pXt, *pX14, *pY5, *pF;
    int *pidx;
    cudaGetSymbolAddress((void**)&pD,   g_D);
    cudaGetSymbolAddress((void**)&pidx, g_idx);
    cudaGetSymbolAddress((void**)&pX0,  g_X0);
    cudaGetSymbolAddress((void**)&pXt,  g_Xt);
    cudaGetSymbolAddress((void**)&pX14, g_X14);
    cudaGetSymbolAddress((void**)&pY5,  g_Y5);
    cudaGetSymbolAddress((void**)&pF,   g_F);

    int nb256 = (N + 255) / 256;
    int nb4   = (N + 3) / 4;
    int nb8   = (N + 7) / 8;
    dim3 gDist((N + TN - 1) / TN, (N + TM - 1) / TM);

    concat_kernel<<<nb256, 256>>>(pts, feats, pX0, N);

    for (int blk = 0; blk < 4; blk++) {
        const float* Xin;
        int lda, C;
        if (blk == 0) { Xin = pX0;                   lda = 4;   C = 4;  }
        else          { Xin = pX14 + (blk - 1) * 64; lda = 256; C = 64; }

        transpose_kernel<<<dim3(nb256, C), 256>>>(Xin, lda, C, pXt, N);
        if (blk == 0)
            sqdist_f2<4><<<gDist, 256>>>(pXt, pD, N, C);
        else
            sqdist_f2<32><<<gDist, 256>>>(pXt, pD, N, C);
        topk_kernel<<<nb8, 256>>>(pD, N, pidx);
        if (blk == 0)
            edge_conv_kernel<4><<<nb4, 256>>>(Xin, lda, W[blk], pidx,
                                              G[blk], Bv[blk], pX14, 0, N);
        else
            edge_conv_kernel<64><<<nb4, 256>>>(Xin, lda, W[blk], pidx,
                                               G[blk], Bv[blk], pX14,
                                               blk * 64, N);
    }

    // conv5: [N,256] x [1024,256]^T -> lrelu(.*g5+b5) -> [N,1024]
    sgemm_nt<EPI_AFF_LRELU><<<dim3((1024 + 63) / 64, (N + 63) / 64), 256>>>(
        pX14, 256, w5, 256, pY5, 1024, N, 1024, 256, g5, b5);
    // feat: [N,1024] x [256,1024]^T -> .*go+bo -> [N,256]
    sgemm_nt<EPI_AFF><<<dim3((256 + 63) / 64, (N + 63) / 64), 256>>>(
        pY5, 1024, wf, 1024, pF, 256, N, 256, 1024, go, bo);
    // head: [N,256] x [20,256]^T + bh -> [N,20]
    sgemm_nt<EPI_AFF><<<dim3(1, (N + 63) / 64), 256>>>(
        pF, 256, wh, 256, outp, 20, N, 20, 256, nullptr, bh);
}

// round 10
// speedup vs baseline: 1.6162x; 1.3042x over previous
#include <cuda_runtime.h>
#include <float.h>
#include <stdint.h>

#define MAXN 12000
#define KNN  20

typedef unsigned long long ull;

// ---------------- scratch (static device globals; no runtime allocation) ---
__device__ int   g_idx[MAXN * KNN];
__device__ float g_X0[MAXN * 4];
__device__ float g_Xt[(size_t)64 * MAXN];       // transposed feature panel
__device__ float g_X14[MAXN * 256];             // x1|x2|x3|x4 concatenated
__device__ float g_Y5[(size_t)MAXN * 1024];
__device__ float g_F[MAXN * 256];

// ---------------- f32x2 packed helpers -------------------------------------
__device__ __forceinline__ ull pack_dup(float x) {
    ull r;
    asm("mov.b64 %0, {%1, %1};" : "=l"(r) : "f"(x));
    return r;
}
__device__ __forceinline__ ull add2(ull a, ull b) {
    ull r;
    asm("add.rn.f32x2 %0, %1, %2;" : "=l"(r) : "l"(a), "l"(b));
    return r;
}
__device__ __forceinline__ ull fma2(ull a, ull b, ull c) {
    ull r;
    asm("fma.rn.f32x2 %0, %1, %2, %3;" : "=l"(r) : "l"(a), "l"(b), "l"(c));
    return r;
}
__device__ __forceinline__ void unpack2(ull v, float& lo, float& hi) {
    asm("mov.b64 {%0, %1}, %2;" : "=f"(lo), "=f"(hi) : "l"(v));
}

// ---------------- transpose: Xt[c][n] = X[n][c] ----------------------------
__global__ void transpose_kernel(const float* __restrict__ X, int lda, int C,
                                 float* __restrict__ Xt, int N)
{
    int n = blockIdx.x * blockDim.x + threadIdx.x;
    int c = blockIdx.y;
    if (n < N && c < C)
        Xt[(size_t)c * N + n] = X[(size_t)n * lda + c];
}

// ---------------- fused kNN: distances + running top-20, no D matrix -------
// Block: 64 m-rows, 256 threads (16 tx cols x 16 ty, 4 rows each).
// Distance chain bit-identical to the passing kernel: ascending-k
// d = add2(a, -b); acc = fma2(d, d, acc). Selection keeps the 20
// lexicographically-smallest (d, idx) per row; output order arbitrary
// (edge-conv max-pool is order-invariant).
#define FTM 64
#define FTN 128

template <int KD>
__global__ void __launch_bounds__(256) fused_knn(
    const float* __restrict__ Xt, int* __restrict__ out, int N)
{
    extern __shared__ __align__(16) char smraw[];
    float* As    = (float*)smraw;                 // [KD][68]
    float* Bs    = As + KD * 68;                  // [KD][132], negated
    float* listD = Bs + KD * 132;                 // [64][20]
    int*   listI = (int*)(listD + 64 * 20);       // [64][20]
    float* bufD  = (float*)(listI + 64 * 20);     // [64][64]
    int*   bufI  = (int*)(bufD + 64 * 64);        // [64][64]
    float* swd   = (float*)(bufI + 64 * 64);      // [64] worst d
    int*   swi   = (int*)(swd + 64);              // [64] worst idx
    int*   ssz   = swi + 64;                      // [64] list size
    int*   sws   = ssz + 64;                      // [64] worst slot
    int*   cnt   = sws + 64;                      // [64] buffer count

    int tid = threadIdx.x;
    int tx = tid & 15;
    int ty = tid >> 4;
    int bm = blockIdx.x * FTM;

    if (tid < 64) {
        swd[tid] = FLT_MAX; swi[tid] = 0x7FFFFFFF;
        ssz[tid] = 0; sws[tid] = 0; cnt[tid] = 0;
    }

    // A panel: once per block
    for (int e = tid; e < KD * 64; e += 256) {
        int k = e >> 6, mm = e & 63;
        int gm = bm + mm;
        As[k * 68 + mm] = (gm < N) ? Xt[(size_t)k * N + gm] : 0.f;
    }
    __syncthreads();

    int ntiles = (N + FTN - 1) / FTN;
    for (int t = 0; t < ntiles; t++) {
        int bn = t * FTN;
        // B panel (negated), float4 coalesced
        for (int e = tid; e < KD * 32; e += 256) {
            int k = e >> 5;
            int nn = (e & 31) * 4;
            int gn = bn + nn;
            float4 v = make_float4(0.f, 0.f, 0.f, 0.f);
            const float* src = Xt + (size_t)k * N;
            if (gn + 3 < N) v = *reinterpret_cast<const float4*>(&src[gn]);
            else {
                if (gn + 0 < N) v.x = src[gn + 0];
                if (gn + 1 < N) v.y = src[gn + 1];
                if (gn + 2 < N) v.z = src[gn + 2];
                if (gn + 3 < N) v.w = src[gn + 3];
            }
            float4 nv = make_float4(-v.x, -v.y, -v.z, -v.w);
            *reinterpret_cast<float4*>(&Bs[k * 132 + nn]) = nv;
        }
        __syncthreads();

        ull acc2[4][4];
#pragma unroll
        for (int i = 0; i < 4; i++)
#pragma unroll
            for (int j = 0; j < 4; j++) acc2[i][j] = 0ULL;

#pragma unroll
        for (int kk = 0; kk < KD; kk++) {
            float4 a4 = *reinterpret_cast<const float4*>(&As[kk * 68 + ty * 4]);
            ulonglong2 b0 = *reinterpret_cast<const ulonglong2*>(&Bs[kk * 132 + tx * 4]);
            ulonglong2 b1 = *reinterpret_cast<const ulonglong2*>(&Bs[kk * 132 + 64 + tx * 4]);
            float ar[4] = { a4.x, a4.y, a4.z, a4.w };
#pragma unroll
            for (int i = 0; i < 4; i++) {
                ull a2 = pack_dup(ar[i]);
                ull d0 = add2(a2, b0.x); acc2[i][0] = fma2(d0, d0, acc2[i][0]);
                ull d1 = add2(a2, b0.y); acc2[i][1] = fma2(d1, d1, acc2[i][1]);
                ull d2 = add2(a2, b1.x); acc2[i][2] = fma2(d2, d2, acc2[i][2]);
                ull d3 = add2(a2, b1.y); acc2[i][3] = fma2(d3, d3, acc2[i][3]);
            }
        }

        // selection: two 64-col halves, threshold filter -> buffer -> merge
#pragma unroll
        for (int cq = 0; cq < 2; cq++) {
#pragma unroll
            for (int i = 0; i < 4; i++) {
                int r = ty * 4 + i;
                float wdv = swd[r];
                int   wiv = swi[r];
#pragma unroll
                for (int pair = 0; pair < 2; pair++) {
                    float d0, d1;
                    unpack2(acc2[i][cq * 2 + pair], d0, d1);
                    int j0 = bn + cq * 64 + tx * 4 + pair * 2;
#pragma unroll
                    for (int e = 0; e < 2; e++) {
                        float d = (e == 0) ? d0 : d1;
                        int   j = j0 + e;
                        if (j < N && ((d < wdv) || (d == wdv && j < wiv))) {
                            int pos = atomicAdd(&cnt[r], 1);
                            bufD[r * 64 + pos] = d;
                            bufI[r * 64 + pos] = j;
                        }
                    }
                }
            }
            __syncthreads();
            if (tid < 64) {
                int r = tid;
                int c = cnt[r];
                if (c > 0) {
                    int sz = ssz[r];
                    float wdv = swd[r]; int wiv = swi[r]; int wsv = sws[r];
                    for (int u = 0; u < c; u++) {
                        float d = bufD[r * 64 + u];
                        int   j = bufI[r * 64 + u];
                        if (sz < KNN) {
                            listD[r * KNN + sz] = d;
                            listI[r * KNN + sz] = j;
                            sz++;
                            if (sz == KNN) {
                                wdv = listD[r * KNN]; wiv = listI[r * KNN]; wsv = 0;
                                for (int q = 1; q < KNN; q++) {
                                    float qd = listD[r * KNN + q];
                                    int   qi = listI[r * KNN + q];
                                    if (qd > wdv || (qd == wdv && qi > wiv)) {
                                        wdv = qd; wiv = qi; wsv = q;
                                    }
                                }
                            }
                        } else if ((d < wdv) || (d == wdv && j < wiv)) {
                            listD[r * KNN + wsv] = d;
                            listI[r * KNN + wsv] = j;
                            wdv = listD[r * KNN]; wiv = listI[r * KNN]; wsv = 0;
                            for (int q = 1; q < KNN; q++) {
                                float qd = listD[r * KNN + q];
                                int   qi = listI[r * KNN + q];
                                if (qd > wdv || (qd == wdv && qi > wiv)) {
                                    wdv = qd; wiv = qi; wsv = q;
                                }
                            }
                        }
                    }
                    ssz[r] = sz;
                    if (sz == KNN) { swd[r] = wdv; swi[r] = wiv; sws[r] = wsv; }
                    cnt[r] = 0;
                }
            }
            __syncthreads();
        }
    }

    if (tid < 64) {
        int m = bm + tid;
        if (m < N) {
#pragma unroll
            for (int s = 0; s < KNN; s++)
                out[m * KNN + s] = listI[tid * KNN + s];
        }
    }
}

// ---------------- generic NT SGEMM (f32x2 packed, exact ascending chains) --
#define TBM 64
#define TBN 64
#define TBK 16

#define EPI_AFF        1
#define EPI_AFF_LRELU  2

template <int EPI>
__global__ void __launch_bounds__(256) sgemm_nt(
    const float* __restrict__ A, int lda,
    const float* __restrict__ B, int ldb,
    float* __restrict__ C, int ldc,
    int M, int N, int Kd,
    const float* __restrict__ gv, const float* __restrict__ bv)
{
    __shared__ __align__(16) float As[TBK][TBM];
    __shared__ __align__(16) float Bs[TBK][TBN];

    int tid = threadIdx.x;
    int bm = blockIdx.y * TBM;
    int bn = blockIdx.x * TBN;
    int tx = tid & 15;
    int ty = tid >> 4;
    int lr = tid >> 2;
    int lk = (tid & 3) * 4;

    ull acc2[4][2];
#pragma unroll
    for (int i = 0; i < 4; i++) { acc2[i][0] = 0ULL; acc2[i][1] = 0ULL; }

    int am  = bm + lr;
    int bnr = bn + lr;

    for (int k0 = 0; k0 < Kd; k0 += TBK) {
#pragma unroll
        for (int i = 0; i < 4; i++) {
            int k = k0 + lk + i;
            As[lk + i][lr] = (am  < M && k < Kd) ? A[(size_t)am  * lda + k] : 0.f;
            Bs[lk + i][lr] = (bnr < N && k < Kd) ? B[(size_t)bnr * ldb + k] : 0.f;
        }
        __syncthreads();
#pragma unroll
        for (int kk = 0; kk < TBK; kk++) {
            float4 a4 = *reinterpret_cast<const float4*>(&As[kk][ty * 4]);
            ulonglong2 bb = *reinterpret_cast<const ulonglong2*>(&Bs[kk][tx * 4]);
            float ar[4] = { a4.x, a4.y, a4.z, a4.w };
#pragma unroll
            for (int i = 0; i < 4; i++) {
                ull a2 = pack_dup(ar[i]);
                acc2[i][0] = fma2(a2, bb.x, acc2[i][0]);
                acc2[i][1] = fma2(a2, bb.y, acc2[i][1]);
            }
        }
        __syncthreads();
    }

#pragma unroll
    for (int i = 0; i < 4; i++) {
        int m = bm + ty * 4 + i;
        if (m >= M) continue;
        float c[4];
        unpack2(acc2[i][0], c[0], c[1]);
        unpack2(acc2[i][1], c[2], c[3]);
#pragma unroll
        for (int j = 0; j < 4; j++) {
            int n = bn + tx * 4 + j;
            if (n >= N) continue;
            float v = c[j];
            float gg = gv ? gv[n] : 1.f;
            float bb = bv ? bv[n] : 0.f;
            v = __fadd_rn(__fmul_rn(v, gg), bb);
            if (EPI == EPI_AFF_LRELU)
                v = (v >= 0.f) ? v : __fmul_rn(0.2f, v);
            C[(size_t)m * ldc + n] = v;
        }
    }
}

// ---------------- helpers ---------------------------------------------------
__global__ void concat_kernel(const float* __restrict__ pts,
                              const float* __restrict__ feat,
                              float* __restrict__ X0, int N)
{
    int n = blockIdx.x * blockDim.x + threadIdx.x;
    if (n >= N) return;
    X0[n * 4 + 0] = pts[n * 3 + 0];
    X0[n * 4 + 1] = pts[n * 3 + 1];
    X0[n * 4 + 2] = pts[n * 3 + 2];
    X0[n * 4 + 3] = feat[n];
}

// ---------------- fused edge conv (exact fp32) -----------------------------
template <int C>
__global__ void __launch_bounds__(256) edge_conv_kernel(
    const float* __restrict__ X, int lda,
    const float* __restrict__ w,      // [64, 2C]
    const int* __restrict__ idx,
    const float* __restrict__ g, const float* __restrict__ b,
    float* __restrict__ out, int colofs, int N)
{
    __shared__ float ws[2 * C][64];
    __shared__ float xs[4][C];
    __shared__ float ds[4][C];

    int tid = threadIdx.x;
    int o = tid & 63;
    int r = tid >> 6;
    int n = blockIdx.x * 4 + r;
    bool active = (n < N);

    for (int e = tid; e < 2 * C * 64; e += 256) {
        int oo = e / (2 * C), cc = e % (2 * C);
        ws[cc][oo] = w[oo * 2 * C + cc];
    }
    if (active) {
        for (int c = o; c < C; c += 64)
            xs[r][c] = X[(size_t)n * lda + c];
    }
    __syncthreads();

    float gg = active ? g[o] : 0.f;
    float bb = active ? b[o] : 0.f;
    float m = -FLT_MAX;
    const int* row = idx + (size_t)(active ? n : 0) * KNN;

    for (int k = 0; k < KNN; k++) {
        int j = active ? row[k] : 0;
        if (active && o < C)
            ds[r][o] = __fsub_rn(X[(size_t)j * lda + o], xs[r][o]);
        __syncthreads();
        if (active) {
            float y = 0.f;
#pragma unroll
            for (int c = 0; c < C; c++)
                y = fmaf(ds[r][c], ws[c][o], y);
#pragma unroll
            for (int c = 0; c < C; c++)
                y = fmaf(xs[r][c], ws[C + c][o], y);
            float z = __fadd_rn(__fmul_rn(y, gg), bb);
            z = (z >= 0.f) ? z : __fmul_rn(0.2f, z);
            m = fmaxf(m, z);
        }
        __syncthreads();
    }
    if (active)
        out[(size_t)n * 256 + colofs + o] = m;
}

// ---------------- launch ----------------------------------------------------
static inline int fused_smem_bytes(int KD) {
    return (KD * 68 + KD * 132 + 64 * 20) * 4 + 64 * 20 * 4
         + 64 * 64 * 4 * 2 + 5 * 64 * 4;
}

extern "C" void kernel_launch(void* const* d_in, const int* in_sizes, int n_in,
                              void* d_out, int out_size)
{
    const float* pts   = (const float*)d_in[0];
    const float* feats = (const float*)d_in[1];
    const float* W[4]  = { (const float*)d_in[2], (const float*)d_in[5],
                           (const float*)d_in[8], (const float*)d_in[11] };
    const float* G[4]  = { (const float*)d_in[3], (const float*)d_in[6],
                           (const float*)d_in[9], (const float*)d_in[12] };
    const float* Bv[4] = { (const float*)d_in[4], (const float*)d_in[7],
                           (const float*)d_in[10], (const float*)d_in[13] };
    const float* w5 = (const float*)d_in[14];
    const float* g5 = (const float*)d_in[15];
    const float* b5 = (const float*)d_in[16];
    const float* wf = (const float*)d_in[17];
    const float* go = (const float*)d_in[18];
    const float* bo = (const float*)d_in[19];
    const float* wh = (const float*)d_in[20];
    const float* bh = (const float*)d_in[21];
    float* outp = (float*)d_out;

    int N = in_sizes[0] / 3;   // 12000

    float *pX0, *pXt, *pX14, *pY5, *pF;
    int *pidx;
    cudaGetSymbolAddress((void**)&pidx, g_idx);
    cudaGetSymbolAddress((void**)&pX0,  g_X0);
    cudaGetSymbolAddress((void**)&pXt,  g_Xt);
    cudaGetSymbolAddress((void**)&pX14, g_X14);
    cudaGetSymbolAddress((void**)&pY5,  g_Y5);
    cudaGetSymbolAddress((void**)&pF,   g_F);

    static bool attr_done = false;
    if (!attr_done) {
        cudaFuncSetAttribute(fused_knn<4>,
            cudaFuncAttributeMaxDynamicSharedMemorySize, fused_smem_bytes(4));
        cudaFuncSetAttribute(fused_knn<64>,
            cudaFuncAttributeMaxDynamicSharedMemorySize, fused_smem_bytes(64));
        attr_done = true;
    }

    int nb256 = (N + 255) / 256;
    int nb4   = (N + 3) / 4;
    int nbM   = (N + FTM - 1) / FTM;

    concat_kernel<<<nb256, 256>>>(pts, feats, pX0, N);

    for (int blk = 0; blk < 4; blk++) {
        const float* Xin;
        int lda, C;
        if (blk == 0) { Xin = pX0;                   lda = 4;   C = 4;  }
        else          { Xin = pX14 + (blk - 1) * 64; lda = 256; C = 64; }

        transpose_kernel<<<dim3(nb256, C), 256>>>(Xin, lda, C, pXt, N);
        if (blk == 0)
            fused_knn<4><<<nbM, 256, fused_smem_bytes(4)>>>(pXt, pidx, N);
        else
            fused_knn<64><<<nbM, 256, fused_smem_bytes(64)>>>(pXt, pidx, N);
        if (blk == 0)
            edge_conv_kernel<4><<<nb4, 256>>>(Xin, lda, W[blk], pidx,
                                              G[blk], Bv[blk], pX14, 0, N);
        else
            edge_conv_kernel<64><<<nb4, 256>>>(Xin, lda, W[blk], pidx,
                                               G[blk], Bv[blk], pX14,
                                               blk * 64, N);
    }

    // conv5: [N,256] x [1024,256]^T -> lrelu(.*g5+b5) -> [N,1024]
    sgemm_nt<EPI_AFF_LRELU><<<dim3((1024 + 63) / 64, (N + 63) / 64), 256>>>(
        pX14, 256, w5, 256, pY5, 1024, N, 1024, 256, g5, b5);
    // feat: [N,1024] x [256,1024]^T -> .*go+bo -> [N,256]
    sgemm_nt<EPI_AFF><<<dim3((256 + 63) / 64, (N + 63) / 64), 256>>>(
        pY5, 1024, wf, 1024, pF, 256, N, 256, 1024, go, bo);
    // head: [N,256] x [20,256]^T + bh -> [N,20]
    sgemm_nt<EPI_AFF><<<dim3(1, (N + 63) / 64), 256>>>(
        pF, 256, wh, 256, outp, 20, N, 20, 256, nullptr, bh);
}

// round 11
// speedup vs baseline: 1.6458x; 1.0183x over previous
#include <cuda_runtime.h>
#include <float.h>
#include <stdint.h>

#define MAXN 12000
#define KNN  20

typedef unsigned long long ull;

// ---------------- scratch (static device globals; no runtime allocation) ---
__device__ int   g_idx[MAXN * KNN];
__device__ float g_X0[MAXN * 4];
__device__ float g_Xt[(size_t)64 * MAXN];       // transposed feature panel
__device__ float g_X14[MAXN * 256];             // x1|x2|x3|x4 concatenated
__device__ float g_Y5[(size_t)MAXN * 1024];
__device__ float g_F[MAXN * 256];

// ---------------- f32x2 packed helpers -------------------------------------
__device__ __forceinline__ ull pack_dup(float x) {
    ull r;
    asm("mov.b64 %0, {%1, %1};" : "=l"(r) : "f"(x));
    return r;
}
__device__ __forceinline__ ull add2(ull a, ull b) {
    ull r;
    asm("add.rn.f32x2 %0, %1, %2;" : "=l"(r) : "l"(a), "l"(b));
    return r;
}
__device__ __forceinline__ ull fma2(ull a, ull b, ull c) {
    ull r;
    asm("fma.rn.f32x2 %0, %1, %2, %3;" : "=l"(r) : "l"(a), "l"(b), "l"(c));
    return r;
}
__device__ __forceinline__ void unpack2(ull v, float& lo, float& hi) {
    asm("mov.b64 {%0, %1}, %2;" : "=f"(lo), "=f"(hi) : "l"(v));
}

// ---------------- fused kNN: distances + running top-20, no D matrix -------
// Block: 64 m-rows, 256 threads. Distance chain bit-identical:
// ascending-k d = add2(a, -b); acc = fma2(d, d, acc). Selection keeps the 20
// lexicographically-smallest (d, idx) per row; output order arbitrary
// (edge-conv max-pool is order-invariant).
#define FTM 64
#define FTN 128

template <int KD>
__global__ void __launch_bounds__(256, 2) fused_knn(
    const float* __restrict__ Xt, int* __restrict__ out, int N)
{
    extern __shared__ __align__(16) char smraw[];
    float* As    = (float*)smraw;                 // [KD][68]
    float* Bs    = As + KD * 68;                  // [KD][132], negated
    float* listD = Bs + KD * 132;                 // [64][20]
    int*   listI = (int*)(listD + 64 * 20);       // [64][20]
    float* bufD  = (float*)(listI + 64 * 20);     // [64][64]
    int*   bufI  = (int*)(bufD + 64 * 64);        // [64][64]
    float* swd   = (float*)(bufI + 64 * 64);      // [64] worst d
    int*   swi   = (int*)(swd + 64);              // [64] worst idx
    int*   ssz   = swi + 64;                      // [64] list size
    int*   sws   = ssz + 64;                      // [64] worst slot
    int*   cnt   = sws + 64;                      // [64] buffer count

    int tid = threadIdx.x;
    int tx = tid & 15;
    int ty = tid >> 4;
    int bm = blockIdx.x * FTM;

    if (tid < 64) {
        swd[tid] = FLT_MAX; swi[tid] = 0x7FFFFFFF;
        ssz[tid] = 0; sws[tid] = 0; cnt[tid] = 0;
    }

    // A panel: once per block
    for (int e = tid; e < KD * 64; e += 256) {
        int k = e >> 6, mm = e & 63;
        int gm = bm + mm;
        As[k * 68 + mm] = (gm < N) ? Xt[(size_t)k * N + gm] : 0.f;
    }
    __syncthreads();

    int ntiles = (N + FTN - 1) / FTN;
    for (int t = 0; t < ntiles; t++) {
        int bn = t * FTN;
        // B panel (negated), float4 coalesced
        for (int e = tid; e < KD * 32; e += 256) {
            int k = e >> 5;
            int nn = (e & 31) * 4;
            int gn = bn + nn;
            float4 v = make_float4(0.f, 0.f, 0.f, 0.f);
            const float* src = Xt + (size_t)k * N;
            if (gn + 3 < N) v = *reinterpret_cast<const float4*>(&src[gn]);
            else {
                if (gn + 0 < N) v.x = src[gn + 0];
                if (gn + 1 < N) v.y = src[gn + 1];
                if (gn + 2 < N) v.z = src[gn + 2];
                if (gn + 3 < N) v.w = src[gn + 3];
            }
            float4 nv = make_float4(-v.x, -v.y, -v.z, -v.w);
            *reinterpret_cast<float4*>(&Bs[k * 132 + nn]) = nv;
        }
        __syncthreads();

        ull acc2[4][4];
#pragma unroll
        for (int i = 0; i < 4; i++)
#pragma unroll
            for (int j = 0; j < 4; j++) acc2[i][j] = 0ULL;

#pragma unroll
        for (int kk = 0; kk < KD; kk++) {
            float4 a4 = *reinterpret_cast<const float4*>(&As[kk * 68 + ty * 4]);
            ulonglong2 b0 = *reinterpret_cast<const ulonglong2*>(&Bs[kk * 132 + tx * 4]);
            ulonglong2 b1 = *reinterpret_cast<const ulonglong2*>(&Bs[kk * 132 + 64 + tx * 4]);
            float ar[4] = { a4.x, a4.y, a4.z, a4.w };
#pragma unroll
            for (int i = 0; i < 4; i++) {
                ull a2 = pack_dup(ar[i]);
                ull d0 = add2(a2, b0.x); acc2[i][0] = fma2(d0, d0, acc2[i][0]);
                ull d1 = add2(a2, b0.y); acc2[i][1] = fma2(d1, d1, acc2[i][1]);
                ull d2 = add2(a2, b1.x); acc2[i][2] = fma2(d2, d2, acc2[i][2]);
                ull d3 = add2(a2, b1.y); acc2[i][3] = fma2(d3, d3, acc2[i][3]);
            }
        }

        // selection: two 64-col halves, threshold filter -> buffer -> merge
#pragma unroll
        for (int cq = 0; cq < 2; cq++) {
#pragma unroll
            for (int i = 0; i < 4; i++) {
                int r = ty * 4 + i;
                float wdv = swd[r];
                int   wiv = swi[r];
#pragma unroll
                for (int pair = 0; pair < 2; pair++) {
                    float d0, d1;
                    unpack2(acc2[i][cq * 2 + pair], d0, d1);
                    int j0 = bn + cq * 64 + tx * 4 + pair * 2;
#pragma unroll
                    for (int e = 0; e < 2; e++) {
                        float d = (e == 0) ? d0 : d1;
                        int   j = j0 + e;
                        if (j < N && ((d < wdv) || (d == wdv && j < wiv))) {
                            int pos = atomicAdd(&cnt[r], 1);
                            bufD[r * 64 + pos] = d;
                            bufI[r * 64 + pos] = j;
                        }
                    }
                }
            }
            __syncthreads();
            if (tid < 64) {
                int r = tid;
                int c = cnt[r];
                if (c > 0) {
                    int sz = ssz[r];
                    float wdv = swd[r]; int wiv = swi[r]; int wsv = sws[r];
                    for (int u = 0; u < c; u++) {
                        float d = bufD[r * 64 + u];
                        int   j = bufI[r * 64 + u];
                        if (sz < KNN) {
                            listD[r * KNN + sz] = d;
                            listI[r * KNN + sz] = j;
                            sz++;
                            if (sz == KNN) {
                                wdv = listD[r * KNN]; wiv = listI[r * KNN]; wsv = 0;
                                for (int q = 1; q < KNN; q++) {
                                    float qd = listD[r * KNN + q];
                                    int   qi = listI[r * KNN + q];
                                    if (qd > wdv || (qd == wdv && qi > wiv)) {
                                        wdv = qd; wiv = qi; wsv = q;
                                    }
                                }
                            }
                        } else if ((d < wdv) || (d == wdv && j < wiv)) {
                            listD[r * KNN + wsv] = d;
                            listI[r * KNN + wsv] = j;
                            wdv = listD[r * KNN]; wiv = listI[r * KNN]; wsv = 0;
                            for (int q = 1; q < KNN; q++) {
                                float qd = listD[r * KNN + q];
                                int   qi = listI[r * KNN + q];
                                if (qd > wdv || (qd == wdv && qi > wiv)) {
                                    wdv = qd; wiv = qi; wsv = q;
                                }
                            }
                        }
                    }
                    ssz[r] = sz;
                    if (sz == KNN) { swd[r] = wdv; swi[r] = wiv; sws[r] = wsv; }
                    cnt[r] = 0;
                }
            }
            __syncthreads();
        }
    }

    if (tid < 64) {
        int m = bm + tid;
        if (m < N) {
#pragma unroll
            for (int s = 0; s < KNN; s++)
                out[m * KNN + s] = listI[tid * KNN + s];
        }
    }
}

// ---------------- generic NT SGEMM (f32x2 packed, exact ascending chains) --
#define TBM 64
#define TBN 64
#define TBK 16

#define EPI_AFF        1
#define EPI_AFF_LRELU  2

template <int EPI>
__global__ void __launch_bounds__(256) sgemm_nt(
    const float* __restrict__ A, int lda,
    const float* __restrict__ B, int ldb,
    float* __restrict__ C, int ldc,
    int M, int N, int Kd,
    const float* __restrict__ gv, const float* __restrict__ bv)
{
    __shared__ __align__(16) float As[TBK][TBM];
    __shared__ __align__(16) float Bs[TBK][TBN];

    int tid = threadIdx.x;
    int bm = blockIdx.y * TBM;
    int bn = blockIdx.x * TBN;
    int tx = tid & 15;
    int ty = tid >> 4;
    int lr = tid >> 2;
    int lk = (tid & 3) * 4;

    ull acc2[4][2];
#pragma unroll
    for (int i = 0; i < 4; i++) { acc2[i][0] = 0ULL; acc2[i][1] = 0ULL; }

    int am  = bm + lr;
    int bnr = bn + lr;

    for (int k0 = 0; k0 < Kd; k0 += TBK) {
#pragma unroll
        for (int i = 0; i < 4; i++) {
            int k = k0 + lk + i;
            As[lk + i][lr] = (am  < M && k < Kd) ? A[(size_t)am  * lda + k] : 0.f;
            Bs[lk + i][lr] = (bnr < N && k < Kd) ? B[(size_t)bnr * ldb + k] : 0.f;
        }
        __syncthreads();
#pragma unroll
        for (int kk = 0; kk < TBK; kk++) {
            float4 a4 = *reinterpret_cast<const float4*>(&As[kk][ty * 4]);
            ulonglong2 bb = *reinterpret_cast<const ulonglong2*>(&Bs[kk][tx * 4]);
            float ar[4] = { a4.x, a4.y, a4.z, a4.w };
#pragma unroll
            for (int i = 0; i < 4; i++) {
                ull a2 = pack_dup(ar[i]);
                acc2[i][0] = fma2(a2, bb.x, acc2[i][0]);
                acc2[i][1] = fma2(a2, bb.y, acc2[i][1]);
            }
        }
        __syncthreads();
    }

#pragma unroll
    for (int i = 0; i < 4; i++) {
        int m = bm + ty * 4 + i;
        if (m >= M) continue;
        float c[4];
        unpack2(acc2[i][0], c[0], c[1]);
        unpack2(acc2[i][1], c[2], c[3]);
#pragma unroll
        for (int j = 0; j < 4; j++) {
            int n = bn + tx * 4 + j;
            if (n >= N) continue;
            float v = c[j];
            float gg = gv ? gv[n] : 1.f;
            float bb = bv ? bv[n] : 0.f;
            v = __fadd_rn(__fmul_rn(v, gg), bb);
            if (EPI == EPI_AFF_LRELU)
                v = (v >= 0.f) ? v : __fmul_rn(0.2f, v);
            C[(size_t)m * ldc + n] = v;
        }
    }
}

// ---------------- helpers ---------------------------------------------------
// concat also writes the transposed panel rows 0..3 (for fused_knn<4>)
__global__ void concat_kernel(const float* __restrict__ pts,
                              const float* __restrict__ feat,
                              float* __restrict__ X0,
                              float* __restrict__ Xt, int N)
{
    int n = blockIdx.x * blockDim.x + threadIdx.x;
    if (n >= N) return;
    float x = pts[n * 3 + 0];
    float y = pts[n * 3 + 1];
    float z = pts[n * 3 + 2];
    float f = feat[n];
    X0[n * 4 + 0] = x;
    X0[n * 4 + 1] = y;
    X0[n * 4 + 2] = z;
    X0[n * 4 + 3] = f;
    Xt[(size_t)0 * N + n] = x;
    Xt[(size_t)1 * N + n] = y;
    Xt[(size_t)2 * N + n] = z;
    Xt[(size_t)3 * N + n] = f;
}

// ---------------- fused edge conv (exact fp32) + transposed output ---------
// Writes out[n][colofs+o] (row-major X14) AND Xt[o][n] (panel for next knn).
template <int C>
__global__ void __launch_bounds__(256) edge_conv_kernel(
    const float* __restrict__ X, int lda,
    const float* __restrict__ w,      // [64, 2C]
    const int* __restrict__ idx,
    const float* __restrict__ g, const float* __restrict__ b,
    float* __restrict__ out, int colofs,
    float* __restrict__ Xt, int N)
{
    __shared__ float ws[2 * C][64];
    __shared__ float xs[4][C];
    __shared__ float ds[4][C];

    int tid = threadIdx.x;
    int o = tid & 63;
    int r = tid >> 6;
    int n = blockIdx.x * 4 + r;
    bool active = (n < N);

    for (int e = tid; e < 2 * C * 64; e += 256) {
        int oo = e / (2 * C), cc = e % (2 * C);
        ws[cc][oo] = w[oo * 2 * C + cc];
    }
    if (active) {
        for (int c = o; c < C; c += 64)
            xs[r][c] = X[(size_t)n * lda + c];
    }
    __syncthreads();

    float gg = active ? g[o] : 0.f;
    float bb = active ? b[o] : 0.f;
    float m = -FLT_MAX;
    const int* row = idx + (size_t)(active ? n : 0) * KNN;

    for (int k = 0; k < KNN; k++) {
        int j = active ? row[k] : 0;
        if (active && o < C)
            ds[r][o] = __fsub_rn(X[(size_t)j * lda + o], xs[r][o]);
        __syncthreads();
        if (active) {
            float y = 0.f;
#pragma unroll
            for (int c = 0; c < C; c++)
                y = fmaf(ds[r][c], ws[c][o], y);
#pragma unroll
            for (int c = 0; c < C; c++)
                y = fmaf(xs[r][c], ws[C + c][o], y);
            float z = __fadd_rn(__fmul_rn(y, gg), bb);
            z = (z >= 0.f) ? z : __fmul_rn(0.2f, z);
            m = fmaxf(m, z);
        }
        __syncthreads();
    }
    if (active) {
        out[(size_t)n * 256 + colofs + o] = m;
        if (Xt) Xt[(size_t)o * N + n] = m;   // transposed panel for next knn
    }
}

// ---------------- launch ----------------------------------------------------
static inline int fused_smem_bytes(int KD) {
    return (KD * 68 + KD * 132 + 64 * 20) * 4 + 64 * 20 * 4
         + 64 * 64 * 4 * 2 + 5 * 64 * 4;
}

extern "C" void kernel_launch(void* const* d_in, const int* in_sizes, int n_in,
                              void* d_out, int out_size)
{
    const float* pts   = (const float*)d_in[0];
    const float* feats = (const float*)d_in[1];
    const float* W[4]  = { (const float*)d_in[2], (const float*)d_in[5],
                           (const float*)d_in[8], (const float*)d_in[11] };
    const float* G[4]  = { (const float*)d_in[3], (const float*)d_in[6],
                           (const float*)d_in[9], (const float*)d_in[12] };
    const float* Bv[4] = { (const float*)d_in[4], (const float*)d_in[7],
                           (const float*)d_in[10], (const float*)d_in[13] };
    const float* w5 = (const float*)d_in[14];
    const float* g5 = (const float*)d_in[15];
    const float* b5 = (const float*)d_in[16];
    const float* wf = (const float*)d_in[17];
    const float* go = (const float*)d_in[18];
    const float* bo = (const float*)d_in[19];
    const float* wh = (const float*)d_in[20];
    const float* bh = (const float*)d_in[21];
    float* outp = (float*)d_out;

    int N = in_sizes[0] / 3;   // 12000

    float *pX0, *pXt, *pX14, *pY5, *pF;
    int *pidx;
    cudaGetSymbolAddress((void**)&pidx, g_idx);
    cudaGetSymbolAddress((void**)&pX0,  g_X0);
    cudaGetSymbolAddress((void**)&pXt,  g_Xt);
    cudaGetSymbolAddress((void**)&pX14, g_X14);
    cudaGetSymbolAddress((void**)&pY5,  g_Y5);
    cudaGetSymbolAddress((void**)&pF,   g_F);

    static bool attr_done = false;
    if (!attr_done) {
        cudaFuncSetAttribute(fused_knn<4>,
            cudaFuncAttributeMaxDynamicSharedMemorySize, fused_smem_bytes(4));
        cudaFuncSetAttribute(fused_knn<64>,
            cudaFuncAttributeMaxDynamicSharedMemorySize, fused_smem_bytes(64));
        attr_done = true;
    }

    int nb256 = (N + 255) / 256;
    int nb4   = (N + 3) / 4;
    int nbM   = (N + FTM - 1) / FTM;

    // L1: concat -> knn4 -> edge4 (edge writes Xt for next layer)
    concat_kernel<<<nb256, 256>>>(pts, feats, pX0, pXt, N);
    fused_knn<4><<<nbM, 256, fused_smem_bytes(4)>>>(pXt, pidx, N);
    edge_conv_kernel<4><<<nb4, 256>>>(pX0, 4, W[0], pidx, G[0], Bv[0],
                                      pX14, 0, pXt, N);

    // L2..L4: knn64 -> edge64 (edge writes Xt for next layer; last writes none)
    for (int blk = 1; blk < 4; blk++) {
        const float* Xin = pX14 + (blk - 1) * 64;
        fused_knn<64><<<nbM, 256, fused_smem_bytes(64)>>>(pXt, pidx, N);
        edge_conv_kernel<64><<<nb4, 256>>>(Xin, 256, W[blk], pidx,
                                           G[blk], Bv[blk], pX14, blk * 64,
                                           (blk < 3) ? pXt : nullptr, N);
    }

    // conv5: [N,256] x [1024,256]^T -> lrelu(.*g5+b5) -> [N,1024]
    sgemm_nt<EPI_AFF_LRELU><<<dim3((1024 + 63) / 64, (N + 63) / 64), 256>>>(
        pX14, 256, w5, 256, pY5, 1024, N, 1024, 256, g5, b5);
    // feat: [N,1024] x [256,1024]^T -> .*go+bo -> [N,256]
    sgemm_nt<EPI_AFF><<<dim3((256 + 63) / 64, (N + 63) / 64), 256>>>(
        pY5, 1024, wf, 1024, pF, 256, N, 256, 1024, go, bo);
    // head: [N,256] x [20,256]^T + bh -> [N,20]
    sgemm_nt<EPI_AFF><<<dim3(1, (N + 63) / 64), 256>>>(
        pF, 256, wh, 256, outp, 20, N, 20, 256, nullptr, bh);
}